// round 13
// baseline (speedup 1.0000x reference)
#include <cuda_runtime.h>

// Sparse CG tensor product:
//   out[b, M[i]] += scale[i] * x[b, M1[i]] * y[b, M2[i]]
//
// Single persistent kernel. One CTA = 32 batch rows/tile, 32 warps; CTA loops
// over tiles. Tiles in smem as [32 rows][stride 513]: gather addr =
// lane*513 + m -> bank (lane + m) mod 32, a permutation => conflict-free.
// Odd stride => scalar fill/drain (conflict-free STS/LDS, coalesced LDG/STG).
//
// Crossbar model (validated R11 vs R12): broadcast LDS charges replicated
// lane-bytes at 128B/cyc. Meta split across two pipes to cut crossbar cost:
//   - index word (M<<22)|(M1<<13)|(M2<<2): broadcast LDS.32 = 1 cyc/path
//   - scale: __shfl_sync from the packing lane's register = 0 crossbar bytes
// Gathers (2 x LDS.32) are now the dominant crossbar term.
//
// M sorted => register accumulation, one smem store per column change. The
// flushed column set is identical for every tile, so the output tile is
// zeroed ONCE and never re-zeroed (overwrite semantics). Per-warp ranges are
// segment-aligned => single writer per column, no atomics.

#define DIMC    512
#define STRIDE  513
#define TILE    (32 * STRIDE)          // 16416 floats
#define NWARP   32
#define NTHR    (NWARP * 32)           // 1024
#define MAXC    7                      // meta chunks held in registers
#define GRID    148

__global__ __launch_bounds__(NTHR, 1)
void tp_kernel(const float* __restrict__ x,
               const float* __restrict__ y,
               const float* __restrict__ scale,
               const int*   __restrict__ M,
               const int*   __restrict__ M1,
               const int*   __restrict__ M2,
               float* __restrict__ out,
               int Brows, int ntiles, int nnz)
{
    extern __shared__ float sm[];
    float* xs = sm;                          // [32][STRIDE]
    float* ys = sm + TILE;
    float* os = sm + 2 * TILE;
    int*   spath = (int*)(sm + 3 * TILE);    // [NWARP][32] index words only

    const int tid  = threadIdx.x;
    const int lane = tid & 31;
    const int warp = tid >> 5;

    // ---- per-warp segment-aligned path range (lane 0 scans, broadcast) ----
    int istart = 0, iend = 0;
    if (lane == 0) {
        istart = (int)(((long long)warp * nnz) / NWARP);
        while (istart > 0 && istart < nnz && M[istart] == M[istart - 1]) istart++;
        iend = (int)(((long long)(warp + 1) * nnz) / NWARP);
        while (iend > 0 && iend < nnz && M[iend] == M[iend - 1]) iend++;
        if (warp == NWARP - 1) iend = nnz;
    }
    istart = __shfl_sync(0xffffffffu, istart, 0);
    iend   = __shfl_sync(0xffffffffu, iend,   0);
    const int npaths  = iend - istart;
    const int nchunks = (npaths + 31) >> 5;

    // ---- pack this warp's metadata into registers (ONCE per kernel) ----
    // lane j of chunk c holds path istart + c*32 + j. Clamped entries repeat
    // the last path's m (no spurious flush) with scale = 0.
    int2 meta[MAXC];
    #pragma unroll
    for (int c = 0; c < MAXC; c++) {
        meta[c] = make_int2(0, 0);
        if ((c << 5) < npaths) {
            int i0 = istart + (c << 5) + lane;
            int ic = min(i0, iend - 1);
            unsigned w = ((unsigned)M[ic] << 22) | ((unsigned)M1[ic] << 13)
                       | ((unsigned)M2[ic] << 2);
            float s = (i0 < iend) ? scale[ic] : 0.f;
            meta[c] = make_int2((int)w, __float_as_int(s));
        }
    }

    // zero output tile ONCE (flushed column set is tile-invariant; flushes
    // overwrite, so no re-zero is ever needed)
    for (int idx = tid; idx < TILE; idx += NTHR) os[idx] = 0.f;

    const bool exact = (Brows == ntiles * 32);   // 20000 = 625*32: true

    for (int t = blockIdx.x; t < ntiles; t += gridDim.x) {
        __syncthreads();                          // prev drain done

        // ---- fill tiles (scalar, conflict-free STS, coalesced LDG) ----
        if (exact) {
            const int gbase = t << 14;            // t * 32 * 512
            #pragma unroll 4
            for (int it = 0; it < 16; it++) {
                int idx = it * NTHR + tid;
                int s = (idx >> 9) * STRIDE + (idx & 511);
                xs[s] = __ldg(x + gbase + idx);
                ys[s] = __ldg(y + gbase + idx);
            }
        } else {
            const int b0 = t << 5;
            for (int idx = tid; idx < 32 * DIMC; idx += NTHR) {
                int b = idx >> 9;
                int d = idx & 511;
                float vx = 0.f, vy = 0.f;
                if (b0 + b < Brows) {
                    vx = x[(b0 + b) * DIMC + d];
                    vy = y[(b0 + b) * DIMC + d];
                }
                int s = b * STRIDE + d;
                xs[s] = vx;
                ys[s] = vy;
            }
        }
        __syncthreads();

        // ---- per-warp path processing ----
        if (npaths > 0) {
            int* sp = spath + (warp << 5);
            const char* xc = (const char*)(xs + lane * STRIDE);
            const char* yc = (const char*)(ys + lane * STRIDE);
            char*       oc = (char*)(os + lane * STRIDE);

            float acc  = 0.f;
            int   mcur = (int)((unsigned)__shfl_sync(0xffffffffu, meta[0].x, 0)
                               >> 22);

            // index word via broadcast LDS.32 (1 crossbar cyc/path);
            // scale via register shuffle (0 crossbar bytes).
            #define DOCHUNK(MV)                                               \
                do {                                                          \
                    sp[lane] = (MV).x;                                        \
                    __syncwarp();                                             \
                    _Pragma("unroll")                                         \
                    for (int j = 0; j < 32; j++) {                            \
                        unsigned w = (unsigned)sp[j];   /* LDS.32 bcast */    \
                        float sv = __int_as_float(                            \
                            __shfl_sync(0xffffffffu, (MV).y, j));             \
                        int mnew = (int)(w >> 22);                            \
                        if (mnew != mcur) {         /* warp-uniform */        \
                            *(float*)(oc + (mcur << 2)) = acc;                \
                            acc  = 0.f;                                       \
                            mcur = mnew;                                      \
                        }                                                     \
                        acc = fmaf(sv * *(const float*)(xc + ((w >> 11) & 0x7FCu)), \
                                   *(const float*)(yc + (w & 0x7FCu)), acc);  \
                    }                                                         \
                    __syncwarp();                                             \
                } while (0)

            #pragma unroll
            for (int c = 0; c < MAXC; c++) {
                if (c < nchunks) DOCHUNK(meta[c]);
            }
            // overflow chunks (only if a warp owns > MAXC*32 paths)
            for (int c = MAXC; c < nchunks; c++) {
                int i0 = istart + (c << 5) + lane;
                int ic = min(i0, iend - 1);
                unsigned w = ((unsigned)M[ic] << 22) | ((unsigned)M1[ic] << 13)
                           | ((unsigned)M2[ic] << 2);
                float s = (i0 < iend) ? scale[ic] : 0.f;
                int2 v = make_int2((int)w, __float_as_int(s));
                DOCHUNK(v);
            }
            #undef DOCHUNK

            *(float*)(oc + (mcur << 2)) = acc;     // final flush
        }
        __syncthreads();

        // ---- drain output tile (scalar LDS, coalesced STG; NO re-zero) ----
        if (exact) {
            const int gbase = t << 14;
            #pragma unroll 4
            for (int it = 0; it < 16; it++) {
                int idx = it * NTHR + tid;
                out[gbase + idx] = os[(idx >> 9) * STRIDE + (idx & 511)];
            }
        } else {
            const int b0 = t << 5;
            for (int idx = tid; idx < 32 * DIMC; idx += NTHR) {
                int b = idx >> 9;
                int d = idx & 511;
                if (b0 + b < Brows)
                    out[(b0 + b) * DIMC + d] = os[b * STRIDE + d];
            }
        }
    }
}

// ---------------------------------------------------------------------------
extern "C" void kernel_launch(void* const* d_in, const int* in_sizes, int n_in,
                              void* d_out, int out_size)
{
    const float* x     = (const float*)d_in[0];
    const float* y     = (const float*)d_in[1];
    const float* scale = (const float*)d_in[2];
    const int*   M     = (const int*)d_in[3];
    const int*   M1    = (const int*)d_in[4];
    const int*   M2    = (const int*)d_in[5];
    float*       out   = (float*)d_out;

    const int B      = in_sizes[0] / DIMC;
    const int nnz    = in_sizes[2];
    const int ntiles = (B + 31) / 32;

    const size_t smem_bytes = (size_t)3 * TILE * sizeof(float)
                            + (size_t)NWARP * 32 * sizeof(int); // 201088 B
    cudaFuncSetAttribute(tp_kernel, cudaFuncAttributeMaxDynamicSharedMemorySize,
                         (int)smem_bytes);

    const int nblocks = (ntiles < GRID) ? ntiles : GRID;
    tp_kernel<<<nblocks, NTHR, smem_bytes>>>(x, y, scale, M, M1, M2, out,
                                             B, ntiles, nnz);
}

// round 14
// speedup vs baseline: 1.0450x; 1.0450x over previous
#include <cuda_runtime.h>

// Sparse CG tensor product:
//   out[b, M[i]] += scale[i] * x[b, M1[i]] * y[b, M2[i]]
//
// Single persistent kernel. One CTA = 32 batch rows/tile, 32 warps; CTA loops
// over tiles. Tiles in smem as [32 rows][stride 513]: gather addr =
// lane*513 + m -> bank (lane + m) mod 32, a permutation => conflict-free.
// Odd stride => scalar fill/drain (conflict-free STS/LDS, coalesced LDG/STG).
//
// Crossbar model (validated R11/R12): broadcast LDS charges replicated
// lane-bytes at 128B/cyc => meta = LDS.64 (2 cyc/path), gathers 2x LDS.32
// (2 cyc/path). That is the byte floor; the residual loss is exposed LDS
// latency per warp. Fix: DUAL independent path streams per warp (64
// segment-aligned ranges across 32 warps), interleaved in the inner loop =>
// 2x independent LDS/FFMA chains in flight per warp.
//
// M sorted => register accumulation, one smem store per column change; all
// ranges segment-aligned => single writer per output column, no atomics.
// Flushed column set is tile-invariant => output tile zeroed ONCE, never
// re-zeroed (flushes overwrite).

#define DIMC    512
#define STRIDE  513
#define TILE    (32 * STRIDE)          // 16416 floats
#define NWARP   32
#define NTHR    (NWARP * 32)           // 1024
#define MAXC    4                      // register meta chunks per stream
#define NSTR    (NWARP * 2)            // 64 path streams (2 per warp)
#define GRID    148

__global__ __launch_bounds__(NTHR, 1)
void tp_kernel(const float* __restrict__ x,
               const float* __restrict__ y,
               const float* __restrict__ scale,
               const int*   __restrict__ M,
               const int*   __restrict__ M1,
               const int*   __restrict__ M2,
               float* __restrict__ out,
               int Brows, int ntiles, int nnz)
{
    extern __shared__ float sm[];
    float* xs = sm;                          // [32][STRIDE]
    float* ys = sm + TILE;
    float* os = sm + 2 * TILE;
    int2*  spath = (int2*)(sm + 3 * TILE);   // [NWARP][64] (A: 0-31, B: 32-63)

    const int tid  = threadIdx.x;
    const int lane = tid & 31;
    const int warp = tid >> 5;

    // ---- two segment-aligned ranges per warp (lanes 0/1 scan, broadcast) ----
    int is_ = 0, ie_ = 0;
    if (lane < 2) {
        int r = warp * 2 + lane;
        is_ = (int)(((long long)r * nnz) / NSTR);
        while (is_ > 0 && is_ < nnz && M[is_] == M[is_ - 1]) is_++;
        ie_ = (int)(((long long)(r + 1) * nnz) / NSTR);
        while (ie_ > 0 && ie_ < nnz && M[ie_] == M[ie_ - 1]) ie_++;
        if (r == NSTR - 1) ie_ = nnz;
    }
    const int isA = __shfl_sync(0xffffffffu, is_, 0);
    const int ieA = __shfl_sync(0xffffffffu, ie_, 0);
    const int isB = __shfl_sync(0xffffffffu, is_, 1);
    const int ieB = __shfl_sync(0xffffffffu, ie_, 1);
    const int lenA = (ieA > isA) ? (ieA - isA) : 0;
    const int lenB = (ieB > isB) ? (ieB - isB) : 0;
    const int nch  = max((lenA + 31) >> 5, (lenB + 31) >> 5);

    // pack word: (M<<22)|(M1<<13)|(M2<<2)  -> byte offsets by shift/mask only
    #define PACKW(i) (((unsigned)M[i] << 22) | ((unsigned)M1[i] << 13) | \
                      ((unsigned)M2[i] << 2))

    const unsigned wlastA = lenA ? PACKW(ieA - 1) : 0u;
    const unsigned wlastB = lenB ? PACKW(ieB - 1) : 0u;

    // ---- register-resident meta (packed once). Pad chunks repeat the last
    //      path's m with scale=0: no spurious flush, FFMA adds 0. ----
    int2 mA[MAXC], mB[MAXC];
    #pragma unroll
    for (int c = 0; c < MAXC; c++) {
        int base = isA + (c << 5);
        if (lenA && base < ieA) {
            int i0 = base + lane, ic = min(i0, ieA - 1);
            mA[c] = make_int2((int)PACKW(ic),
                              (i0 < ieA) ? __float_as_int(scale[ic]) : 0);
        } else mA[c] = make_int2((int)wlastA, 0);
        base = isB + (c << 5);
        if (lenB && base < ieB) {
            int i0 = base + lane, ic = min(i0, ieB - 1);
            mB[c] = make_int2((int)PACKW(ic),
                              (i0 < ieB) ? __float_as_int(scale[ic]) : 0);
        } else mB[c] = make_int2((int)wlastB, 0);
    }

    // zero output tile ONCE (flush set is tile-invariant; flushes overwrite)
    for (int idx = tid; idx < TILE; idx += NTHR) os[idx] = 0.f;

    const bool exact = (Brows == ntiles * 32);   // 20000 = 625*32: true

    for (int t = blockIdx.x; t < ntiles; t += gridDim.x) {
        __syncthreads();                          // prev drain done

        // ---- fill tiles (scalar, conflict-free STS, coalesced LDG) ----
        if (exact) {
            const int gbase = t << 14;            // t * 32 * 512
            #pragma unroll 4
            for (int it = 0; it < 16; it++) {
                int idx = it * NTHR + tid;
                int s = (idx >> 9) * STRIDE + (idx & 511);
                xs[s] = __ldg(x + gbase + idx);
                ys[s] = __ldg(y + gbase + idx);
            }
        } else {
            const int b0 = t << 5;
            for (int idx = tid; idx < 32 * DIMC; idx += NTHR) {
                int b = idx >> 9;
                int d = idx & 511;
                float vx = 0.f, vy = 0.f;
                if (b0 + b < Brows) {
                    vx = x[(b0 + b) * DIMC + d];
                    vy = y[(b0 + b) * DIMC + d];
                }
                int s = b * STRIDE + d;
                xs[s] = vx;
                ys[s] = vy;
            }
        }
        __syncthreads();

        // ---- dual-stream path processing ----
        if (nch > 0) {
            int2* sp = spath + (warp << 6);
            const char* xc = (const char*)(xs + lane * STRIDE);
            const char* yc = (const char*)(ys + lane * STRIDE);
            char*       oc = (char*)(os + lane * STRIDE);

            float a0 = 0.f, a1 = 0.f;
            int mc0 = (int)((unsigned)__shfl_sync(0xffffffffu, mA[0].x, 0) >> 22);
            int mc1 = (int)((unsigned)__shfl_sync(0xffffffffu, mB[0].x, 0) >> 22);

            #define PROC(P, ACC, MC)                                          \
                do {                                                          \
                    unsigned w_ = (unsigned)(P).x;                            \
                    int mn_ = (int)(w_ >> 22);                                \
                    if (mn_ != (MC)) {            /* warp-uniform */          \
                        *(float*)(oc + ((MC) << 2)) = (ACC);                  \
                        (ACC) = 0.f;                                          \
                        (MC)  = mn_;                                          \
                    }                                                         \
                    (ACC) = fmaf(__int_as_float((P).y)                        \
                                   * *(const float*)(xc + ((w_ >> 11) & 0x7FCu)), \
                                 *(const float*)(yc + (w_ & 0x7FCu)), (ACC)); \
                } while (0)

            #define DOCHUNK(VA, VB)                                           \
                do {                                                          \
                    sp[lane]      = (VA);                                     \
                    sp[lane + 32] = (VB);                                     \
                    __syncwarp();                                             \
                    _Pragma("unroll")                                         \
                    for (int j = 0; j < 32; j++) {                            \
                        int2 pa = sp[j];          /* broadcast LDS.64 */      \
                        int2 pb = sp[j + 32];     /* independent stream */    \
                        PROC(pa, a0, mc0);                                    \
                        PROC(pb, a1, mc1);                                    \
                    }                                                         \
                    __syncwarp();                                             \
                } while (0)

            #pragma unroll
            for (int c = 0; c < MAXC; c++) {
                if (c < nch) DOCHUNK(mA[c], mB[c]);
            }
            // overflow chunks (rare: range > MAXC*32 paths) — restage gmem
            for (int c = MAXC; c < nch; c++) {
                int2 vA, vB;
                int base = isA + (c << 5);
                if (lenA && base < ieA) {
                    int i0 = base + lane, ic = min(i0, ieA - 1);
                    vA = make_int2((int)PACKW(ic),
                                   (i0 < ieA) ? __float_as_int(scale[ic]) : 0);
                } else vA = make_int2((int)wlastA, 0);
                base = isB + (c << 5);
                if (lenB && base < ieB) {
                    int i0 = base + lane, ic = min(i0, ieB - 1);
                    vB = make_int2((int)PACKW(ic),
                                   (i0 < ieB) ? __float_as_int(scale[ic]) : 0);
                } else vB = make_int2((int)wlastB, 0);
                DOCHUNK(vA, vB);
            }
            #undef DOCHUNK
            #undef PROC

            if (lenA) *(float*)(oc + (mc0 << 2)) = a0;   // final flushes
            if (lenB) *(float*)(oc + (mc1 << 2)) = a1;
        }
        __syncthreads();

        // ---- drain output tile (scalar LDS, coalesced STG; NO re-zero) ----
        if (exact) {
            const int gbase = t << 14;
            #pragma unroll 4
            for (int it = 0; it < 16; it++) {
                int idx = it * NTHR + tid;
                out[gbase + idx] = os[(idx >> 9) * STRIDE + (idx & 511)];
            }
        } else {
            const int b0 = t << 5;
            for (int idx = tid; idx < 32 * DIMC; idx += NTHR) {
                int b = idx >> 9;
                int d = idx & 511;
                if (b0 + b < Brows)
                    out[(b0 + b) * DIMC + d] = os[b * STRIDE + d];
            }
        }
    }
    #undef PACKW
}

// ---------------------------------------------------------------------------
extern "C" void kernel_launch(void* const* d_in, const int* in_sizes, int n_in,
                              void* d_out, int out_size)
{
    const float* x     = (const float*)d_in[0];
    const float* y     = (const float*)d_in[1];
    const float* scale = (const float*)d_in[2];
    const int*   M     = (const int*)d_in[3];
    const int*   M1    = (const int*)d_in[4];
    const int*   M2    = (const int*)d_in[5];
    float*       out   = (float*)d_out;

    const int B      = in_sizes[0] / DIMC;
    const int nnz    = in_sizes[2];
    const int ntiles = (B + 31) / 32;

    const size_t smem_bytes = (size_t)3 * TILE * sizeof(float)
                            + (size_t)NWARP * 64 * sizeof(int2); // 213376 B
    cudaFuncSetAttribute(tp_kernel, cudaFuncAttributeMaxDynamicSharedMemorySize,
                         (int)smem_bytes);

    const int nblocks = (ntiles < GRID) ? ntiles : GRID;
    tp_kernel<<<nblocks, NTHR, smem_bytes>>>(x, y, scale, M, M1, M2, out,
                                             B, ntiles, nnz);
}

// round 15
// speedup vs baseline: 1.0733x; 1.0271x over previous
#include <cuda_runtime.h>

// Sparse CG tensor product:
//   out[b, M[i]] += scale[i] * x[b, M1[i]] * y[b, M2[i]]
//
// Single persistent kernel. One CTA = 32 batch rows/tile, 32 warps; CTA loops
// over tiles. Tiles in smem as [32 rows][stride 513]: gather addr =
// lane*513 + m -> bank (lane + m) mod 32, a permutation => conflict-free.
// Odd stride => scalar fill/drain (conflict-free STS/LDS, coalesced LDG/STG).
//
// Meta word per path: flag(31) | m(22..30) | m1(13..21) | m2<<2(2..12), with
// flag = "M changed vs previous path" (precomputed). Per 32-path chunk the
// warp publishes {word, scale} once (STS.64) and consumes TWO paths per
// broadcast LDS.128 (same crossbar bytes as 2x LDS.64, half the issue slots).
// Flush test is a sign-bit compare; the flushed column comes from the
// previous word (live register, free in the unrolled body). Two alternating
// accumulators halve the serial FFMA chain; they join only at flushes.
//
// M sorted => register accumulation; per-warp ranges segment-aligned =>
// single writer per output column, no atomics. Flushed column set is
// tile-invariant => output tile zeroed ONCE (flushes overwrite).

#define DIMC    512
#define STRIDE  513
#define TILE    (32 * STRIDE)          // 16416 floats
#define NWARP   32
#define NTHR    (NWARP * 32)           // 1024
#define MAXC    7                      // register meta chunks (<=224 paths)
#define GRID    148

__global__ __launch_bounds__(NTHR, 1)
void tp_kernel(const float* __restrict__ x,
               const float* __restrict__ y,
               const float* __restrict__ scale,
               const int*   __restrict__ M,
               const int*   __restrict__ M1,
               const int*   __restrict__ M2,
               float* __restrict__ out,
               int Brows, int ntiles, int nnz)
{
    extern __shared__ float sm[];
    float* xs = sm;                          // [32][STRIDE]
    float* ys = sm + TILE;
    float* os = sm + 2 * TILE;
    int2*  spath = (int2*)(sm + 3 * TILE);   // [NWARP][32]

    const int tid  = threadIdx.x;
    const int lane = tid & 31;
    const int warp = tid >> 5;

    // ---- per-warp segment-aligned path range (lane 0 scans, broadcast) ----
    int is_ = 0, ie_ = 0;
    if (lane == 0) {
        is_ = (int)(((long long)warp * nnz) / NWARP);
        while (is_ > 0 && is_ < nnz && M[is_] == M[is_ - 1]) is_++;
        ie_ = (int)(((long long)(warp + 1) * nnz) / NWARP);
        while (ie_ > 0 && ie_ < nnz && M[ie_] == M[ie_ - 1]) ie_++;
        if (warp == NWARP - 1) ie_ = nnz;
    }
    const int istart = __shfl_sync(0xffffffffu, is_, 0);
    const int iend   = __shfl_sync(0xffffffffu, ie_, 0);
    const int npaths = iend - istart;
    const int nch    = (npaths + 31) >> 5;

    // ---- register-resident meta, packed once. Lane j of chunk c holds path
    //      istart + c*32 + j; clamped pads repeat the last path's indices with
    //      scale = 0 and flag = 0 (no spurious flush, FFMA adds 0). ----
    int2 meta[MAXC];
    #pragma unroll
    for (int c = 0; c < MAXC; c++) {
        meta[c] = make_int2(0, 0);
        if ((c << 5) < npaths) {
            int i0 = istart + (c << 5) + lane;
            int ic = min(i0, iend - 1);
            unsigned w = ((unsigned)M[ic] << 22) | ((unsigned)M1[ic] << 13)
                       | ((unsigned)M2[ic] << 2);
            float s = 0.f;
            if (i0 < iend) {
                s = scale[ic];
                if (ic > istart && M[ic] != M[ic - 1]) w |= 0x80000000u;
            }
            meta[c] = make_int2((int)w, __float_as_int(s));
        }
    }

    // zero output tile ONCE (flush set is tile-invariant; flushes overwrite)
    for (int idx = tid; idx < TILE; idx += NTHR) os[idx] = 0.f;

    const bool exact = (Brows == ntiles * 32);   // 20000 = 625*32: true

    for (int t = blockIdx.x; t < ntiles; t += gridDim.x) {
        // ---- fill tiles (scalar, conflict-free STS, coalesced LDG).
        //      No loop-top sync needed: drain(t-1) read os only; the barrier
        //      below orders it before compute(t)'s os writes. ----
        if (exact) {
            const int gbase = t << 14;            // t * 32 * 512
            #pragma unroll 4
            for (int it = 0; it < 16; it++) {
                int idx = it * NTHR + tid;
                int s = (idx >> 9) * STRIDE + (idx & 511);
                xs[s] = __ldg(x + gbase + idx);
                ys[s] = __ldg(y + gbase + idx);
            }
        } else {
            const int b0 = t << 5;
            for (int idx = tid; idx < 32 * DIMC; idx += NTHR) {
                int b = idx >> 9;
                int d = idx & 511;
                float vx = 0.f, vy = 0.f;
                if (b0 + b < Brows) {
                    vx = x[(b0 + b) * DIMC + d];
                    vy = y[(b0 + b) * DIMC + d];
                }
                int s = b * STRIDE + d;
                xs[s] = vx;
                ys[s] = vy;
            }
        }
        __syncthreads();

        // ---- per-warp path processing ----
        if (npaths > 0) {
            int2* sp = spath + (warp << 5);
            const char* xc = (const char*)(xs + lane * STRIDE);
            const char* yc = (const char*)(ys + lane * STRIDE);
            char*       oc = (char*)(os + lane * STRIDE);

            float a0 = 0.f, a1 = 0.f;
            unsigned wprev = (unsigned)__shfl_sync(0xffffffffu, meta[0].x, 0);

            // two paths per LDS.128; flush on sign bit; prev column from the
            // previous word register ((w>>20)&0x7FC = m<<2, flag masked off).
            #define DOCHUNK(MV)                                               \
                do {                                                          \
                    sp[lane] = (MV);                                          \
                    __syncwarp();                                             \
                    const int4* sq = (const int4*)sp;                         \
                    _Pragma("unroll")                                         \
                    for (int j = 0; j < 16; j++) {                            \
                        int4 q = sq[j];            /* 2 paths, LDS.128 */     \
                        unsigned wa = (unsigned)q.x;                          \
                        unsigned wb = (unsigned)q.z;                          \
                        if ((int)wa < 0) {         /* warp-uniform */         \
                            *(float*)(oc + ((wprev >> 20) & 0x7FCu)) = a0 + a1; \
                            a0 = 0.f; a1 = 0.f;                               \
                        }                                                     \
                        a0 = fmaf(__int_as_float(q.y)                         \
                                    * *(const float*)(xc + ((wa >> 11) & 0x7FCu)), \
                                  *(const float*)(yc + (wa & 0x7FCu)), a0);   \
                        if ((int)wb < 0) {                                    \
                            *(float*)(oc + ((wa >> 20) & 0x7FCu)) = a0 + a1;  \
                            a0 = 0.f; a1 = 0.f;                               \
                        }                                                     \
                        a1 = fmaf(__int_as_float(q.w)                         \
                                    * *(const float*)(xc + ((wb >> 11) & 0x7FCu)), \
                                  *(const float*)(yc + (wb & 0x7FCu)), a1);   \
                        wprev = wb;                                           \
                    }                                                         \
                    __syncwarp();                                             \
                } while (0)

            #pragma unroll
            for (int c = 0; c < MAXC; c++) {
                if (c < nch) DOCHUNK(meta[c]);
            }
            // overflow chunks (only if a range exceeds MAXC*32 paths)
            for (int c = MAXC; c < nch; c++) {
                int i0 = istart + (c << 5) + lane;
                int ic = min(i0, iend - 1);
                unsigned w = ((unsigned)M[ic] << 22) | ((unsigned)M1[ic] << 13)
                           | ((unsigned)M2[ic] << 2);
                float s = 0.f;
                if (i0 < iend) {
                    s = scale[ic];
                    if (ic > istart && M[ic] != M[ic - 1]) w |= 0x80000000u;
                }
                int2 v = make_int2((int)w, __float_as_int(s));
                DOCHUNK(v);
            }
            #undef DOCHUNK

            // final flush (pads repeat the last real column => correct addr)
            *(float*)(oc + ((wprev >> 20) & 0x7FCu)) = a0 + a1;
        }
        __syncthreads();

        // ---- drain output tile (scalar LDS, coalesced STG; NO re-zero) ----
        if (exact) {
            const int gbase = t << 14;
            #pragma unroll 4
            for (int it = 0; it < 16; it++) {
                int idx = it * NTHR + tid;
                out[gbase + idx] = os[(idx >> 9) * STRIDE + (idx & 511)];
            }
        } else {
            const int b0 = t << 5;
            for (int idx = tid; idx < 32 * DIMC; idx += NTHR) {
                int b = idx >> 9;
                int d = idx & 511;
                if (b0 + b < Brows)
                    out[(b0 + b) * DIMC + d] = os[b * STRIDE + d];
            }
        }
    }
}

// ---------------------------------------------------------------------------
extern "C" void kernel_launch(void* const* d_in, const int* in_sizes, int n_in,
                              void* d_out, int out_size)
{
    const float* x     = (const float*)d_in[0];
    const float* y     = (const float*)d_in[1];
    const float* scale = (const float*)d_in[2];
    const int*   M     = (const int*)d_in[3];
    const int*   M1    = (const int*)d_in[4];
    const int*   M2    = (const int*)d_in[5];
    float*       out   = (float*)d_out;

    const int B      = in_sizes[0] / DIMC;
    const int nnz    = in_sizes[2];
    const int ntiles = (B + 31) / 32;

    const size_t smem_bytes = (size_t)3 * TILE * sizeof(float)
                            + (size_t)NWARP * 32 * sizeof(int2); // 205184 B
    cudaFuncSetAttribute(tp_kernel, cudaFuncAttributeMaxDynamicSharedMemorySize,
                         (int)smem_bytes);

    const int nblocks = (ntiles < GRID) ? ntiles : GRID;
    tp_kernel<<<nblocks, NTHR, smem_bytes>>>(x, y, scale, M, M1, M2, out,
                                             B, ntiles, nnz);
}

// round 16
// speedup vs baseline: 1.1140x; 1.0379x over previous
#include <cuda_runtime.h>

// Sparse CG tensor product:
//   out[b, M[i]] += scale[i] * x[b, M1[i]] * y[b, M2[i]]
//
// Single persistent kernel. One CTA = 32 batch rows/tile, 32 warps; CTA loops
// over tiles. Tiles in smem as [32 rows][stride 513]: gather addr =
// lane*513 + m -> bank (lane + m) mod 32, a permutation => conflict-free.
// Odd stride => scalar fill/drain (conflict-free STS/LDS, coalesced LDG/STG).
//
// Meta packed to 8B/path {(M<<22)|(M1<<13)|(M2<<2), scale}, held in registers
// (packed once), published per 32-path chunk via STS.64 and consumed as
// broadcast LDS.64 (2 crossbar cyc/path). Unpack is shift/mask only.
// Dual alternating accumulators halve the serial FFMA chain; flush stores
// a0+a1 on column change (M sorted => register accumulation works).
// Per-warp ranges segment-aligned => single writer per column, no atomics.
// Flushed column set is tile-invariant => output tile zeroed ONCE (flushes
// overwrite; no re-zero). Two barriers per tile.

#define DIMC    512
#define STRIDE  513
#define TILE    (32 * STRIDE)          // 16416 floats
#define NWARP   32
#define NTHR    (NWARP * 32)           // 1024
#define MAXC    7                      // register meta chunks (<=224 paths)
#define GRID    148

__global__ __launch_bounds__(NTHR, 1)
void tp_kernel(const float* __restrict__ x,
               const float* __restrict__ y,
               const float* __restrict__ scale,
               const int*   __restrict__ M,
               const int*   __restrict__ M1,
               const int*   __restrict__ M2,
               float* __restrict__ out,
               int Brows, int ntiles, int nnz)
{
    extern __shared__ float sm[];
    float* xs = sm;                          // [32][STRIDE]
    float* ys = sm + TILE;
    float* os = sm + 2 * TILE;
    int2*  spath = (int2*)(sm + 3 * TILE);   // [NWARP][32]

    const int tid  = threadIdx.x;
    const int lane = tid & 31;
    const int warp = tid >> 5;

    // ---- per-warp segment-aligned path range (lane 0 scans, broadcast) ----
    int is_ = 0, ie_ = 0;
    if (lane == 0) {
        is_ = (int)(((long long)warp * nnz) / NWARP);
        while (is_ > 0 && is_ < nnz && M[is_] == M[is_ - 1]) is_++;
        ie_ = (int)(((long long)(warp + 1) * nnz) / NWARP);
        while (ie_ > 0 && ie_ < nnz && M[ie_] == M[ie_ - 1]) ie_++;
        if (warp == NWARP - 1) ie_ = nnz;
    }
    const int istart = __shfl_sync(0xffffffffu, is_, 0);
    const int iend   = __shfl_sync(0xffffffffu, ie_, 0);
    const int npaths = iend - istart;
    const int nch    = (npaths + 31) >> 5;

    // ---- register-resident meta, packed once. Lane j of chunk c holds path
    //      istart + c*32 + j; clamped pads repeat the last path's m (no
    //      spurious flush) with scale = 0 (FFMA adds 0). ----
    int2 meta[MAXC];
    #pragma unroll
    for (int c = 0; c < MAXC; c++) {
        meta[c] = make_int2(0, 0);
        if ((c << 5) < npaths) {
            int i0 = istart + (c << 5) + lane;
            int ic = min(i0, iend - 1);
            unsigned w = ((unsigned)M[ic] << 22) | ((unsigned)M1[ic] << 13)
                       | ((unsigned)M2[ic] << 2);
            float s = (i0 < iend) ? scale[ic] : 0.f;
            meta[c] = make_int2((int)w, __float_as_int(s));
        }
    }

    // zero output tile ONCE (flush set is tile-invariant; flushes overwrite)
    for (int idx = tid; idx < TILE; idx += NTHR) os[idx] = 0.f;

    const bool exact = (Brows == ntiles * 32);   // 20000 = 625*32: true

    for (int t = blockIdx.x; t < ntiles; t += gridDim.x) {
        // ---- fill tiles (scalar, conflict-free STS, coalesced LDG).
        //      No loop-top sync: drain(t-1) only READ os; the barrier below
        //      orders it before compute(t)'s os writes. ----
        if (exact) {
            const int gbase = t << 14;            // t * 32 * 512
            #pragma unroll 4
            for (int it = 0; it < 16; it++) {
                int idx = it * NTHR + tid;
                int s = (idx >> 9) * STRIDE + (idx & 511);
                xs[s] = __ldg(x + gbase + idx);
                ys[s] = __ldg(y + gbase + idx);
            }
        } else {
            const int b0 = t << 5;
            for (int idx = tid; idx < 32 * DIMC; idx += NTHR) {
                int b = idx >> 9;
                int d = idx & 511;
                float vx = 0.f, vy = 0.f;
                if (b0 + b < Brows) {
                    vx = x[(b0 + b) * DIMC + d];
                    vy = y[(b0 + b) * DIMC + d];
                }
                int s = b * STRIDE + d;
                xs[s] = vx;
                ys[s] = vy;
            }
        }
        __syncthreads();

        // ---- per-warp path processing ----
        if (npaths > 0) {
            int2* sp = spath + (warp << 5);
            const char* xc = (const char*)(xs + lane * STRIDE);
            const char* yc = (const char*)(ys + lane * STRIDE);
            char*       oc = (char*)(os + lane * STRIDE);

            float a0 = 0.f, a1 = 0.f;
            int   mcur = (int)((unsigned)__shfl_sync(0xffffffffu, meta[0].x, 0)
                               >> 22);

            // index+scale via broadcast LDS.64 (2 crossbar cyc/path);
            // dual accumulators by path parity; flush stores a0+a1.
            #define DOCHUNK(MV)                                               \
                do {                                                          \
                    sp[lane] = (MV);                                          \
                    __syncwarp();                                             \
                    _Pragma("unroll")                                         \
                    for (int j = 0; j < 32; j += 2) {                         \
                        int2 p0 = sp[j];                                      \
                        int2 p1 = sp[j + 1];                                  \
                        unsigned w0 = (unsigned)p0.x;                         \
                        int mn0 = (int)(w0 >> 22);                            \
                        if (mn0 != mcur) {          /* warp-uniform */        \
                            *(float*)(oc + (mcur << 2)) = a0 + a1;            \
                            a0 = 0.f; a1 = 0.f;                               \
                            mcur = mn0;                                       \
                        }                                                     \
                        a0 = fmaf(__int_as_float(p0.y)                        \
                                    * *(const float*)(xc + ((w0 >> 11) & 0x7FCu)), \
                                  *(const float*)(yc + (w0 & 0x7FCu)), a0);   \
                        unsigned w1 = (unsigned)p1.x;                         \
                        int mn1 = (int)(w1 >> 22);                            \
                        if (mn1 != mcur) {                                    \
                            *(float*)(oc + (mcur << 2)) = a0 + a1;            \
                            a0 = 0.f; a1 = 0.f;                               \
                            mcur = mn1;                                       \
                        }                                                     \
                        a1 = fmaf(__int_as_float(p1.y)                        \
                                    * *(const float*)(xc + ((w1 >> 11) & 0x7FCu)), \
                                  *(const float*)(yc + (w1 & 0x7FCu)), a1);   \
                    }                                                         \
                    __syncwarp();                                             \
                } while (0)

            #pragma unroll
            for (int c = 0; c < MAXC; c++) {
                if (c < nch) DOCHUNK(meta[c]);
            }
            // overflow chunks (only if a range exceeds MAXC*32 paths)
            for (int c = MAXC; c < nch; c++) {
                int i0 = istart + (c << 5) + lane;
                int ic = min(i0, iend - 1);
                unsigned w = ((unsigned)M[ic] << 22) | ((unsigned)M1[ic] << 13)
                           | ((unsigned)M2[ic] << 2);
                float s = (i0 < iend) ? scale[ic] : 0.f;
                int2 v = make_int2((int)w, __float_as_int(s));
                DOCHUNK(v);
            }
            #undef DOCHUNK

            *(float*)(oc + (mcur << 2)) = a0 + a1;   // final flush
        }
        __syncthreads();

        // ---- drain output tile (scalar LDS, coalesced STG; NO re-zero) ----
        if (exact) {
            const int gbase = t << 14;
            #pragma unroll 4
            for (int it = 0; it < 16; it++) {
                int idx = it * NTHR + tid;
                out[gbase + idx] = os[(idx >> 9) * STRIDE + (idx & 511)];
            }
        } else {
            const int b0 = t << 5;
            for (int idx = tid; idx < 32 * DIMC; idx += NTHR) {
                int b = idx >> 9;
                int d = idx & 511;
                if (b0 + b < Brows)
                    out[(b0 + b) * DIMC + d] = os[b * STRIDE + d];
            }
        }
    }
}

// ---------------------------------------------------------------------------
extern "C" void kernel_launch(void* const* d_in, const int* in_sizes, int n_in,
                              void* d_out, int out_size)
{
    const float* x     = (const float*)d_in[0];
    const float* y     = (const float*)d_in[1];
    const float* scale = (const float*)d_in[2];
    const int*   M     = (const int*)d_in[3];
    const int*   M1    = (const int*)d_in[4];
    const int*   M2    = (const int*)d_in[5];
    float*       out   = (float*)d_out;

    const int B      = in_sizes[0] / DIMC;
    const int nnz    = in_sizes[2];
    const int ntiles = (B + 31) / 32;

    const size_t smem_bytes = (size_t)3 * TILE * sizeof(float)
                            + (size_t)NWARP * 32 * sizeof(int2); // 205184 B
    cudaFuncSetAttribute(tp_kernel, cudaFuncAttributeMaxDynamicSharedMemorySize,
                         (int)smem_bytes);

    const int nblocks = (ntiles < GRID) ? ntiles : GRID;
    tp_kernel<<<nblocks, NTHR, smem_bytes>>>(x, y, scale, M, M1, M2, out,
                                             B, ntiles, nnz);
}